// round 1
// baseline (speedup 1.0000x reference)
#include <cuda_runtime.h>
#include <math.h>

// Problem constants (fixed by the reference's setup_inputs)
#define T  4096        // B*S tokens
#define D  2048
#define E  8
#define H  704
#define TD (T * D)     // 8388608 output elements for y
#define PAIRS (T * 2)  // total (token, expert) pairs with top-k = 2

// ---------------- device scratch (no allocation allowed) ----------------
__device__ float g_h[PAIRS * H];   // scaled hidden: s * silu(g) * u, 23 MB
__device__ int   g_tok[E * T];     // per-expert token lists
__device__ float g_s[E * T];       // per-expert gate scores
__device__ int   g_cnt[E];
__device__ int   g_off[E];
__device__ float g_imp[E];         // importance sums

// ---------------- kernel 0: zero output + accumulators ----------------
__global__ void k_zero(float* __restrict__ y) {
    long i = (long)blockIdx.x * blockDim.x + threadIdx.x;
    long stride = (long)gridDim.x * blockDim.x;
    for (; i < TD; i += stride) y[i] = 0.f;
    if (blockIdx.x == 0 && threadIdx.x < E) {
        g_cnt[threadIdx.x] = 0;
        g_imp[threadIdx.x] = 0.f;
    }
}

// ---------------- kernel 1: gate ----------------
// logits = tanh(x @ Wg1) @ Wg2 ; top-2 ; softmax over the 2 ; build lists.
// One block handles 64 tokens. 256 threads.
__global__ void k_gate(const float* __restrict__ x,
                       const float* __restrict__ Wg1,
                       const float* __restrict__ Wg2) {
    __shared__ float xs[64][33];     // padded to kill bank conflicts
    __shared__ float wgs[32][8];
    __shared__ float h1[64][8];
    __shared__ float wg2s[64];
    int tid = threadIdx.x;
    int t0 = blockIdx.x * 64;
    int tt = tid >> 2, eq = tid & 3;   // 4 threads per token, 2 experts each
    if (tid < 64) wg2s[tid] = Wg2[tid];
    float a0 = 0.f, a1 = 0.f;
    for (int d0 = 0; d0 < D; d0 += 32) {
#pragma unroll
        for (int i = 0; i < 8; i++) {
            int idx = tid + i * 256;
            int r = idx >> 5, c = idx & 31;
            xs[r][c] = x[(long)(t0 + r) * D + d0 + c];
        }
        wgs[tid >> 3][tid & 7] = Wg1[(long)(d0 + (tid >> 3)) * E + (tid & 7)];
        __syncthreads();
#pragma unroll
        for (int kk = 0; kk < 32; kk++) {
            float xv = xs[tt][kk];
            a0 = fmaf(xv, wgs[kk][eq * 2],     a0);
            a1 = fmaf(xv, wgs[kk][eq * 2 + 1], a1);
        }
        __syncthreads();
    }
    h1[tt][eq * 2]     = tanhf(a0);
    h1[tt][eq * 2 + 1] = tanhf(a1);
    __syncthreads();
    if (tid < 64) {
        int t = t0 + tid;
        float l[E];
#pragma unroll
        for (int e = 0; e < E; e++) {
            float s = 0.f;
#pragma unroll
            for (int j = 0; j < E; j++) s = fmaf(h1[tid][j], wg2s[j * E + e], s);
            l[e] = s;
        }
        // top-2 (strict > -> lowest index on ties, matches jax.lax.top_k)
        int i1 = 0; float v1 = l[0];
#pragma unroll
        for (int e = 1; e < E; e++) if (l[e] > v1) { v1 = l[e]; i1 = e; }
        int i2 = -1; float v2 = -1e30f;
#pragma unroll
        for (int e = 0; e < E; e++) if (e != i1 && l[e] > v2) { v2 = l[e]; i2 = e; }
        float s1 = 1.f / (1.f + expf(v2 - v1));  // softmax over {v1, v2}
        float s2 = 1.f - s1;
        atomicAdd(&g_imp[i1], s1);
        atomicAdd(&g_imp[i2], s2);
        int p1 = atomicAdd(&g_cnt[i1], 1);
        g_tok[i1 * T + p1] = t; g_s[i1 * T + p1] = s1;
        int p2 = atomicAdd(&g_cnt[i2], 1);
        g_tok[i2 * T + p2] = t; g_s[i2 * T + p2] = s2;
    }
}

// ---------------- kernel 2: offsets + balance loss ----------------
__global__ void k_mid(float* __restrict__ y, int out_size) {
    if (threadIdx.x == 0) {
        int off = 0;
        for (int e = 0; e < E; e++) { g_off[e] = off; off += g_cnt[e]; }
        float mi = 0.f, ml = 0.f;
        for (int e = 0; e < E; e++) { mi += g_imp[e]; ml += (float)g_cnt[e]; }
        mi /= E; ml /= E;
        float vi = 0.f, vl = 0.f;
        for (int e = 0; e < E; e++) {
            float di = g_imp[e] - mi;       vi += di * di;
            float dl = (float)g_cnt[e] - ml; vl += dl * dl;
        }
        vi /= (E - 1);  // ddof = 1 (torch-style unbiased var)
        vl /= (E - 1);
        float loss = 0.01f * (vi / (mi * mi + 1e-10f) + vl / (ml * ml + 1e-10f));
        if (out_size > TD) y[TD] = loss;
    }
}

// ---------------- kernel 3: grouped gate/up GEMM + SwiGLU ----------------
// Per expert e: Xe[cnt_e, D] @ {W_gate[e], W_up[e]} (D x H).
// Block tile: 64 tokens x 64 H. 256 threads, 4x4 per thread per GEMM.
// Epilogue folds the gate score: h = s * silu(g) * u  -> pass 2 is plain GEMM.
__global__ void k_expert1(const float* __restrict__ x,
                          const float* __restrict__ Wg,
                          const float* __restrict__ Wu) {
    int e = blockIdx.z;
    int cnt = g_cnt[e];
    int ts = blockIdx.y * 64;
    if (ts >= cnt) return;
    int h0 = blockIdx.x * 64;
    __shared__ float Xs[64][17];
    __shared__ float Wgs[16][64];
    __shared__ float Wus[16][64];
    __shared__ int   toks[64];
    __shared__ float ss[64];
    int tid = threadIdx.x;
    if (tid < 64) {
        int gi = ts + tid;
        toks[tid] = (gi < cnt) ? g_tok[e * T + gi] : 0;     // clamp: dummy row 0
        ss[tid]   = (gi < cnt) ? g_s[e * T + gi] : 0.f;
    }
    __syncthreads();
    int ty = tid >> 4, tx = tid & 15;
    float ag[4][4] = {};
    float au[4][4] = {};
    const float* wg_e = Wg + (long)e * D * H;
    const float* wu_e = Wu + (long)e * D * H;
    for (int d0 = 0; d0 < D; d0 += 16) {
#pragma unroll
        for (int i = 0; i < 4; i++) {                       // X tile (gathered)
            int idx = tid + i * 256;
            int r = idx >> 4, c = idx & 15;
            Xs[r][c] = x[(long)toks[r] * D + d0 + c];
        }
#pragma unroll
        for (int i = 0; i < 4; i++) {                       // W tiles (coalesced)
            int idx = tid + i * 256;
            int r = idx >> 6, c = idx & 63;
            Wgs[r][c] = wg_e[(long)(d0 + r) * H + h0 + c];
            Wus[r][c] = wu_e[(long)(d0 + r) * H + h0 + c];
        }
        __syncthreads();
#pragma unroll
        for (int kk = 0; kk < 16; kk++) {
            float xv[4];
#pragma unroll
            for (int i = 0; i < 4; i++) xv[i] = Xs[ty * 4 + i][kk];
            float4 wg4 = ((const float4*)Wgs[kk])[tx];      // conflict-free LDS.128
            float4 wu4 = ((const float4*)Wus[kk])[tx];
            float wgv[4] = {wg4.x, wg4.y, wg4.z, wg4.w};
            float wuv[4] = {wu4.x, wu4.y, wu4.z, wu4.w};
#pragma unroll
            for (int i = 0; i < 4; i++)
#pragma unroll
                for (int j = 0; j < 4; j++) {
                    ag[i][j] = fmaf(xv[i], wgv[j], ag[i][j]);
                    au[i][j] = fmaf(xv[i], wuv[j], au[i][j]);
                }
        }
        __syncthreads();
    }
    int off = g_off[e];
#pragma unroll
    for (int i = 0; i < 4; i++) {
        int li = ty * 4 + i;
        int gi = ts + li;
        if (gi < cnt) {
            float s = ss[li];
            long base = (long)(off + gi) * H + h0 + tx * 4;
#pragma unroll
            for (int j = 0; j < 4; j++) {
                float g = ag[i][j], u = au[i][j];
                float sig = 1.f / (1.f + expf(-g));
                g_h[base + j] = s * g * sig * u;            // s * silu(g) * u
            }
        }
    }
}

// ---------------- kernel 4: grouped down GEMM + scatter-add ----------------
// Per expert e: He[cnt_e, H] @ W_down[e] (H x D) -> atomicAdd into y rows.
__global__ void k_expert2(const float* __restrict__ Wd, float* __restrict__ y) {
    int e = blockIdx.z;
    int cnt = g_cnt[e];
    int ts = blockIdx.y * 64;
    if (ts >= cnt) return;
    int d0 = blockIdx.x * 64;
    __shared__ float Hs[64][17];
    __shared__ float Wds[16][64];
    __shared__ int   toks[64];
    int tid = threadIdx.x;
    if (tid < 64) {
        int gi = ts + tid;
        toks[tid] = (gi < cnt) ? g_tok[e * T + gi] : -1;
    }
    __syncthreads();
    int ty = tid >> 4, tx = tid & 15;
    float a[4][4] = {};
    int off = g_off[e];
    const float* wd_e = Wd + (long)e * H * D;
    for (int k0 = 0; k0 < H; k0 += 16) {                    // 704 = 44 * 16
#pragma unroll
        for (int i = 0; i < 4; i++) {
            int idx = tid + i * 256;
            int r = idx >> 4, c = idx & 15;
            int gi = ts + r;
            int pr = (gi < cnt) ? (off + gi) : off;         // clamp
            Hs[r][c] = g_h[(long)pr * H + k0 + c];
        }
#pragma unroll
        for (int i = 0; i < 4; i++) {
            int idx = tid + i * 256;
            int r = idx >> 6, c = idx & 63;
            Wds[r][c] = wd_e[(long)(k0 + r) * D + d0 + c];
        }
        __syncthreads();
#pragma unroll
        for (int kk = 0; kk < 16; kk++) {
            float hv[4];
#pragma unroll
            for (int i = 0; i < 4; i++) hv[i] = Hs[ty * 4 + i][kk];
            float4 w4 = ((const float4*)Wds[kk])[tx];
            float wv[4] = {w4.x, w4.y, w4.z, w4.w};
#pragma unroll
            for (int i = 0; i < 4; i++)
#pragma unroll
                for (int j = 0; j < 4; j++)
                    a[i][j] = fmaf(hv[i], wv[j], a[i][j]);
        }
        __syncthreads();
    }
#pragma unroll
    for (int i = 0; i < 4; i++) {
        int li = ty * 4 + i;
        int tok = toks[li];
        if (tok >= 0) {
            long base = (long)tok * D + d0 + tx * 4;
#pragma unroll
            for (int j = 0; j < 4; j++)
                atomicAdd(&y[base + j], a[i][j]);           // 2 adds/elem total
        }
    }
}

// ---------------- launch ----------------
extern "C" void kernel_launch(void* const* d_in, const int* in_sizes, int n_in,
                              void* d_out, int out_size) {
    const float* x   = (const float*)d_in[0];
    const float* Wg1 = (const float*)d_in[1];
    const float* Wg2 = (const float*)d_in[2];
    const float* Wg  = (const float*)d_in[3];
    const float* Wu  = (const float*)d_in[4];
    const float* Wd  = (const float*)d_in[5];
    float* y = (float*)d_out;

    k_zero<<<2048, 256>>>(y);
    k_gate<<<T / 64, 256>>>(x, Wg1, Wg2);
    k_mid<<<1, 32>>>(y, out_size);
    dim3 g1(H / 64, T / 64, E);   // (11, 64, 8); blocks beyond cnt_e exit early
    k_expert1<<<g1, 256>>>(x, Wg, Wu);
    dim3 g2(D / 64, T / 64, E);   // (32, 64, 8)
    k_expert2<<<g2, 256>>>(Wd, y);
}

// round 4
// speedup vs baseline: 3.7989x; 3.7989x over previous
#include <cuda_runtime.h>
#include <cuda_fp16.h>
#include <cstdint>
#include <math.h>

#define T 4096
#define D 2048
#define E 8
#define H 704
#define TD (T*D)
#define PAIRS (T*2)

// ---------------- device scratch ----------------
__device__ float g_h[PAIRS*H];   // s*silu(g)*u  (23 MB)
__device__ float g_o[PAIRS*D];   // per-pair down output (67 MB)
__device__ int   g_tok[E*T];
__device__ float g_s[E*T];
__device__ int   g_cnt[E];
__device__ int   g_off[E];
__device__ float g_imp[E];
__device__ int   g_pe[PAIRS];
__device__ int   g_pp[PAIRS];

// ---------------- helpers ----------------
__device__ __forceinline__ uint32_t su32(const void* p) {
    return (uint32_t)__cvta_generic_to_shared(p);
}
__device__ __forceinline__ uint32_t pkh2(float lo, float hi) {
    uint32_t r;
    asm("{.reg .b16 l,h; cvt.rn.f16.f32 l,%1; cvt.rn.f16.f32 h,%2; mov.b32 %0,{l,h};}"
        : "=r"(r) : "f"(lo), "f"(hi));
    return r;
}
#define LDSM4(r0,r1,r2,r3,a) \
    asm volatile("ldmatrix.sync.aligned.m8n8.x4.shared.b16 {%0,%1,%2,%3},[%4];" \
        : "=r"(r0),"=r"(r1),"=r"(r2),"=r"(r3) : "r"(a))
#define LDSM4T(r0,r1,r2,r3,a) \
    asm volatile("ldmatrix.sync.aligned.m8n8.x4.trans.shared.b16 {%0,%1,%2,%3},[%4];" \
        : "=r"(r0),"=r"(r1),"=r"(r2),"=r"(r3) : "r"(a))
#define MMA(d,a,b) \
    asm("mma.sync.aligned.m16n8k16.row.col.f32.f16.f16.f32 " \
        "{%0,%1,%2,%3},{%4,%5,%6,%7},{%8,%9},{%0,%1,%2,%3};" \
        : "+f"((d)[0]),"+f"((d)[1]),"+f"((d)[2]),"+f"((d)[3]) \
        : "r"((a)[0]),"r"((a)[1]),"r"((a)[2]),"r"((a)[3]),"r"((b)[0]),"r"((b)[1]))

// ---------------- small kernels ----------------
__global__ void k_init() {
    if (threadIdx.x < E) { g_cnt[threadIdx.x] = 0; g_imp[threadIdx.x] = 0.f; }
}

__global__ void k_gate(const float* __restrict__ x, const float* __restrict__ Wg1,
                       const float* __restrict__ Wg2) {
    __shared__ float xs[64][33];
    __shared__ float wgs[32][8];
    __shared__ float h1[64][8];
    __shared__ float wg2s[64];
    int tid = threadIdx.x, t0 = blockIdx.x * 64;
    int tt = tid >> 2, eq = tid & 3;
    if (tid < 64) wg2s[tid] = Wg2[tid];
    float a0 = 0.f, a1 = 0.f;
    for (int d0 = 0; d0 < D; d0 += 32) {
#pragma unroll
        for (int i = 0; i < 8; i++) {
            int idx = tid + i * 256, r = idx >> 5, c = idx & 31;
            xs[r][c] = x[(long)(t0 + r) * D + d0 + c];
        }
        wgs[tid >> 3][tid & 7] = Wg1[(long)(d0 + (tid >> 3)) * E + (tid & 7)];
        __syncthreads();
#pragma unroll
        for (int kk = 0; kk < 32; kk++) {
            float xv = xs[tt][kk];
            a0 = fmaf(xv, wgs[kk][eq * 2],     a0);
            a1 = fmaf(xv, wgs[kk][eq * 2 + 1], a1);
        }
        __syncthreads();
    }
    h1[tt][eq * 2]     = tanhf(a0);
    h1[tt][eq * 2 + 1] = tanhf(a1);
    __syncthreads();
    if (tid < 64) {
        int t = t0 + tid;
        float l[E];
#pragma unroll
        for (int e = 0; e < E; e++) {
            float s = 0.f;
#pragma unroll
            for (int j = 0; j < E; j++) s = fmaf(h1[tid][j], wg2s[j * E + e], s);
            l[e] = s;
        }
        int i1 = 0; float v1 = l[0];
#pragma unroll
        for (int e = 1; e < E; e++) if (l[e] > v1) { v1 = l[e]; i1 = e; }
        int i2 = -1; float v2 = -1e30f;
#pragma unroll
        for (int e = 0; e < E; e++) if (e != i1 && l[e] > v2) { v2 = l[e]; i2 = e; }
        float s1 = 1.f / (1.f + expf(v2 - v1));
        float s2 = 1.f - s1;
        atomicAdd(&g_imp[i1], s1);
        atomicAdd(&g_imp[i2], s2);
        int p1 = atomicAdd(&g_cnt[i1], 1);
        g_tok[i1 * T + p1] = t; g_s[i1 * T + p1] = s1;
        int p2 = atomicAdd(&g_cnt[i2], 1);
        g_tok[i2 * T + p2] = t; g_s[i2 * T + p2] = s2;
        g_pe[2 * t] = i1;     g_pp[2 * t] = p1;
        g_pe[2 * t + 1] = i2; g_pp[2 * t + 1] = p2;
    }
}

__global__ void k_mid(float* __restrict__ y, int out_size) {
    if (threadIdx.x == 0) {
        int off = 0;
        for (int e = 0; e < E; e++) { g_off[e] = off; off += g_cnt[e]; }
        float mi = 0.f, ml = 0.f;
        for (int e = 0; e < E; e++) { mi += g_imp[e]; ml += (float)g_cnt[e]; }
        mi /= E; ml /= E;
        float vi = 0.f, vl = 0.f;
        for (int e = 0; e < E; e++) {
            float di = g_imp[e] - mi;        vi += di * di;
            float dl = (float)g_cnt[e] - ml; vl += dl * dl;
        }
        vi /= (E - 1); vl /= (E - 1);
        float loss = 0.01f * (vi / (mi * mi + 1e-10f) + vl / (ml * ml + 1e-10f));
        if (out_size > TD) y[TD] = loss;
    }
}

// ============ expert1: X[128] @ {Wg,Wu}[:,h0:h0+64], SwiGLU, -> g_h ============
// 8 warps: wm=wid&3 (32 rows), wn=wid>>2 (32 of the 64 h-cols); each warp holds
// matching gate AND up accумs -> local epilogue.
__global__ void __launch_bounds__(256) k_e1(const float* __restrict__ x,
                                            const float* __restrict__ Wg,
                                            const float* __restrict__ Wu) {
    __shared__ half As[2][128 * 40];       // [row][k] pad 32->40
    __shared__ half Bs[2][2][32 * 72];     // [mat][k][n] pad 64->72
    __shared__ int   toks[128];
    __shared__ float ssm[128];
    int e = blockIdx.z, cnt = g_cnt[e], ts = blockIdx.y * 128;
    if (ts >= cnt) return;
    int h0 = blockIdx.x * 64;
    int tid = threadIdx.x, wid = tid >> 5, lane = tid & 31;
    if (tid < 128) {
        int gi = ts + tid;
        toks[tid] = (gi < cnt) ? g_tok[e * T + gi] : g_tok[e * T];
        ssm[tid]  = (gi < cnt) ? g_s[e * T + gi] : 0.f;
    }
    __syncthreads();
    const float* wg_e = Wg + (size_t)e * D * H + h0;
    const float* wu_e = Wu + (size_t)e * D * H + h0;

    int ar = tid >> 1, ak = (tid & 1) * 16;            // A: 2 thr/row, 16 k each
    const float* agm = x + (size_t)toks[ar] * D + ak;
    int br = tid >> 3, bc = (tid & 7) * 8;             // B: row 0..31, 8 cols
    const float* bgm_g = wg_e + (size_t)br * H + bc;
    const float* bgm_u = wu_e + (size_t)br * H + bc;

    float4 pa[4], pg[2], pu[2];
    float ag_[2][4][4] = {}, au_[2][4][4] = {};
    int wm = wid & 3, wn = wid >> 2;

    // prologue: chunk 0 -> buf 0
#pragma unroll
    for (int j = 0; j < 4; j++) pa[j] = *(const float4*)(agm + j * 4);
    pg[0] = *(const float4*)(bgm_g);     pg[1] = *(const float4*)(bgm_g + 4);
    pu[0] = *(const float4*)(bgm_u);     pu[1] = *(const float4*)(bgm_u + 4);
    {
        uint32_t* ad = (uint32_t*)&As[0][ar * 40 + ak];
#pragma unroll
        for (int j = 0; j < 4; j++) { ad[j*2] = pkh2(pa[j].x, pa[j].y); ad[j*2+1] = pkh2(pa[j].z, pa[j].w); }
        uint32_t* bg = (uint32_t*)&Bs[0][0][br * 72 + bc];
        uint32_t* bu = (uint32_t*)&Bs[0][1][br * 72 + bc];
        bg[0]=pkh2(pg[0].x,pg[0].y); bg[1]=pkh2(pg[0].z,pg[0].w); bg[2]=pkh2(pg[1].x,pg[1].y); bg[3]=pkh2(pg[1].z,pg[1].w);
        bu[0]=pkh2(pu[0].x,pu[0].y); bu[1]=pkh2(pu[0].z,pu[0].w); bu[2]=pkh2(pu[1].x,pu[1].y); bu[3]=pkh2(pu[1].z,pu[1].w);
    }
    __syncthreads();

    for (int it = 0; it < 64; it++) {
        int buf = it & 1;
        if (it < 63) {            // prefetch next chunk into regs
            size_t k0 = (size_t)(it + 1) * 32;
#pragma unroll
            for (int j = 0; j < 4; j++) pa[j] = *(const float4*)(agm + k0 + j * 4);
            pg[0] = *(const float4*)(bgm_g + k0 * H); pg[1] = *(const float4*)(bgm_g + k0 * H + 4);
            pu[0] = *(const float4*)(bgm_u + k0 * H); pu[1] = *(const float4*)(bgm_u + k0 * H + 4);
        }
        uint32_t sA  = su32(&As[buf][0]);
        uint32_t sBg = su32(&Bs[buf][0][0]);
        uint32_t sBu = su32(&Bs[buf][1][0]);
#pragma unroll
        for (int kq = 0; kq < 2; kq++) {
            int k0 = kq * 16;
            uint32_t a[2][4], bg[4][2], bu[4][2];
#pragma unroll
            for (int mi = 0; mi < 2; mi++)
                LDSM4(a[mi][0], a[mi][1], a[mi][2], a[mi][3],
                      sA + ((wm*32 + mi*16 + (lane & 15)) * 40 + k0 + ((lane >> 4) << 3)) * 2);
#pragma unroll
            for (int nj = 0; nj < 2; nj++) {
                uint32_t ao = ((k0 + (lane & 15)) * 72 + wn*32 + nj*16 + ((lane >> 4) << 3)) * 2;
                LDSM4T(bg[nj*2][0], bg[nj*2][1], bg[nj*2+1][0], bg[nj*2+1][1], sBg + ao);
                LDSM4T(bu[nj*2][0], bu[nj*2][1], bu[nj*2+1][0], bu[nj*2+1][1], sBu + ao);
            }
#pragma unroll
            for (int mi = 0; mi < 2; mi++)
#pragma unroll
                for (int ni = 0; ni < 4; ni++) {
                    MMA(ag_[mi][ni], a[mi], bg[ni]);
                    MMA(au_[mi][ni], a[mi], bu[ni]);
                }
        }
        if (it < 63) {            // store prefetched into other buffer
            int nb = buf ^ 1;
            uint32_t* ad = (uint32_t*)&As[nb][ar * 40 + ak];
#pragma unroll
            for (int j = 0; j < 4; j++) { ad[j*2] = pkh2(pa[j].x, pa[j].y); ad[j*2+1] = pkh2(pa[j].z, pa[j].w); }
            uint32_t* bgd = (uint32_t*)&Bs[nb][0][br * 72 + bc];
            uint32_t* bud = (uint32_t*)&Bs[nb][1][br * 72 + bc];
            bgd[0]=pkh2(pg[0].x,pg[0].y); bgd[1]=pkh2(pg[0].z,pg[0].w); bgd[2]=pkh2(pg[1].x,pg[1].y); bgd[3]=pkh2(pg[1].z,pg[1].w);
            bud[0]=pkh2(pu[0].x,pu[0].y); bud[1]=pkh2(pu[0].z,pu[0].w); bud[2]=pkh2(pu[1].x,pu[1].y); bud[3]=pkh2(pu[1].z,pu[1].w);
        }
        __syncthreads();
    }
    // epilogue: h = s * silu(g) * u
    int off = g_off[e];
#pragma unroll
    for (int mi = 0; mi < 2; mi++)
#pragma unroll
        for (int hr = 0; hr < 2; hr++) {
            int m = wm*32 + mi*16 + (lane >> 2) + hr*8;
            int gi = ts + m;
            if (gi < cnt) {
                float s = ssm[m];
                float* dst = g_h + (size_t)(off + gi) * H + h0 + wn*32 + (lane & 3) * 2;
#pragma unroll
                for (int ni = 0; ni < 4; ni++) {
                    float gv0 = ag_[mi][ni][hr*2], gv1 = ag_[mi][ni][hr*2+1];
                    float uv0 = au_[mi][ni][hr*2], uv1 = au_[mi][ni][hr*2+1];
                    float2 o;
                    o.x = s * gv0 * (1.f / (1.f + expf(-gv0))) * uv0;
                    o.y = s * gv1 * (1.f / (1.f + expf(-gv1))) * uv1;
                    *(float2*)(dst + ni * 8) = o;
                }
            }
        }
}

// ============ expert2: g_h rows @ W_down[e][:, d0:d0+128] -> g_o ============
__global__ void __launch_bounds__(256) k_e2(const float* __restrict__ Wd) {
    __shared__ half As[2][128 * 40];       // pad 32->40
    __shared__ half Bs[2][32 * 136];       // [k][n] pad 128->136
    __shared__ int prow[128];
    int e = blockIdx.z, cnt = g_cnt[e], ts = blockIdx.y * 128;
    if (ts >= cnt) return;
    int d0 = blockIdx.x * 128;
    int tid = threadIdx.x, wid = tid >> 5, lane = tid & 31;
    int off = g_off[e];
    if (tid < 128) {
        int gi = ts + tid;
        prow[tid] = off + ((gi < cnt) ? gi : 0);
    }
    __syncthreads();
    const float* wd_e = Wd + (size_t)e * H * D + d0;

    int ar = tid >> 1, ak = (tid & 1) * 16;
    const float* agm = g_h + (size_t)prow[ar] * H + ak;
    int br = tid >> 3, bc = (tid & 7) * 16;
    const float* bgm = wd_e + (size_t)br * D + bc;

    float4 pa[4], pb[4];
    float acc[2][8][4] = {};
    int wm = wid & 3, wn = wid >> 2;

#pragma unroll
    for (int j = 0; j < 4; j++) pa[j] = *(const float4*)(agm + j * 4);
#pragma unroll
    for (int j = 0; j < 4; j++) pb[j] = *(const float4*)(bgm + j * 4);
    {
        uint32_t* ad = (uint32_t*)&As[0][ar * 40 + ak];
#pragma unroll
        for (int j = 0; j < 4; j++) { ad[j*2] = pkh2(pa[j].x, pa[j].y); ad[j*2+1] = pkh2(pa[j].z, pa[j].w); }
        uint32_t* bd = (uint32_t*)&Bs[0][br * 136 + bc];
#pragma unroll
        for (int j = 0; j < 4; j++) { bd[j*2] = pkh2(pb[j].x, pb[j].y); bd[j*2+1] = pkh2(pb[j].z, pb[j].w); }
    }
    __syncthreads();

    const int NIT = H / 32;  // 22
    for (int it = 0; it < NIT; it++) {
        int buf = it & 1;
        if (it < NIT - 1) {
            size_t k0 = (size_t)(it + 1) * 32;
#pragma unroll
            for (int j = 0; j < 4; j++) pa[j] = *(const float4*)(agm + k0 + j * 4);
#pragma unroll
            for (int j = 0; j < 4; j++) pb[j] = *(const float4*)(bgm + k0 * D + j * 4);
        }
        uint32_t sA = su32(&As[buf][0]);
        uint32_t sB = su32(&Bs[buf][0]);
#pragma unroll
        for (int kq = 0; kq < 2; kq++) {
            int k0 = kq * 16;
            uint32_t a[2][4], bf[8][2];
#pragma unroll
            for (int mi = 0; mi < 2; mi++)
                LDSM4(a[mi][0], a[mi][1], a[mi][2], a[mi][3],
                      sA + ((wm*32 + mi*16 + (lane & 15)) * 40 + k0 + ((lane >> 4) << 3)) * 2);
#pragma unroll
            for (int nj = 0; nj < 4; nj++) {
                uint32_t ao = ((k0 + (lane & 15)) * 136 + wn*64 + nj*16 + ((lane >> 4) << 3)) * 2;
                LDSM4T(bf[nj*2][0], bf[nj*2][1], bf[nj*2+1][0], bf[nj*2+1][1], sB + ao);
            }
#pragma unroll
            for (int mi = 0; mi < 2; mi++)
#pragma unroll
                for (int ni = 0; ni < 8; ni++)
                    MMA(acc[mi][ni], a[mi], bf[ni]);
        }
        if (it < NIT - 1) {
            int nb = buf ^ 1;
            uint32_t* ad = (uint32_t*)&As[nb][ar * 40 + ak];
#pragma unroll
            for (int j = 0; j < 4; j++) { ad[j*2] = pkh2(pa[j].x, pa[j].y); ad[j*2+1] = pkh2(pa[j].z, pa[j].w); }
            uint32_t* bd = (uint32_t*)&Bs[nb][br * 136 + bc];
#pragma unroll
            for (int j = 0; j < 4; j++) { bd[j*2] = pkh2(pb[j].x, pb[j].y); bd[j*2+1] = pkh2(pb[j].z, pb[j].w); }
        }
        __syncthreads();
    }
#pragma unroll
    for (int mi = 0; mi < 2; mi++)
#pragma unroll
        for (int hr = 0; hr < 2; hr++) {
            int m = wm*32 + mi*16 + (lane >> 2) + hr*8;
            int gi = ts + m;
            if (gi < cnt) {
                float* dst = g_o + (size_t)(off + gi) * D + d0 + wn*64 + (lane & 3) * 2;
#pragma unroll
                for (int ni = 0; ni < 8; ni++) {
                    float2 o;
                    o.x = acc[mi][ni][hr*2];
                    o.y = acc[mi][ni][hr*2+1];
                    *(float2*)(dst + ni * 8) = o;
                }
            }
        }
}

// ---------------- combine: y[t] = g_o[row1] + g_o[row2] ----------------
__global__ void k_combine(float* __restrict__ y) {
    __shared__ int offs[E];
    if (threadIdx.x < E) offs[threadIdx.x] = g_off[threadIdx.x];
    __syncthreads();
    int idx = blockIdx.x * blockDim.x + threadIdx.x;
    int t = idx >> 9;                 // 512 float4 per token
    int d4 = idx & 511;
    int r1 = offs[g_pe[2 * t]] + g_pp[2 * t];
    int r2 = offs[g_pe[2 * t + 1]] + g_pp[2 * t + 1];
    float4 a = *(const float4*)(g_o + (size_t)r1 * D + d4 * 4);
    float4 b = *(const float4*)(g_o + (size_t)r2 * D + d4 * 4);
    *(float4*)(y + (size_t)t * D + d4 * 4) =
        make_float4(a.x + b.x, a.y + b.y, a.z + b.z, a.w + b.w);
}

// ---------------- launch ----------------
extern "C" void kernel_launch(void* const* d_in, const int* in_sizes, int n_in,
                              void* d_out, int out_size) {
    const float* x   = (const float*)d_in[0];
    const float* Wg1 = (const float*)d_in[1];
    const float* Wg2 = (const float*)d_in[2];
    const float* Wg  = (const float*)d_in[3];
    const float* Wu  = (const float*)d_in[4];
    const float* Wd  = (const float*)d_in[5];
    float* y = (float*)d_out;

    k_init<<<1, 32>>>();
    k_gate<<<T / 64, 256>>>(x, Wg1, Wg2);
    k_mid<<<1, 32>>>(y, out_size);
    dim3 g1(H / 64, T / 128, E);   // (11, 32, 8)
    k_e1<<<g1, 256>>>(x, Wg, Wu);
    dim3 g2(D / 128, T / 128, E);  // (16, 32, 8)
    k_e2<<<g2, 256>>>(Wd);
    k_combine<<<TD / 1024, 256>>>(y);
}